// round 9
// baseline (speedup 1.0000x reference)
#include <cuda_runtime.h>
#include <math.h>

// Problem constants: B=32, T=512, C=128, K=3, lags 8..64 (57), CYC_MAX=P_MAX=64,
// KW=9, GN: 32 groups of 4 channels.

#define TT 512
#define CC 128
#define BB 32
#define NN 96           // B*K
#define NLAG 57
#define NCHUNK 8        // autocorr t-chunks
#define FCHUNK 32       // final-stage t-chunks (16 rows each)
#define ST 577          // prefix rows per b (indices 0..576)

// ---------------- device scratch (no allocations allowed) ----------------
__device__ float g_rp[BB * NCHUNK * 64];     // partial autocorr [b][chunk][lag]
__device__ int   g_p[NN];                    // periods
__device__ float g_wk[NN];                   // softmax weights
__device__ float g_gm[BB];                   // Gamma per b
__device__ float g_hg[NN * 64 * CC];         // gated conv output [n][l][c]
__device__ float g_part[BB * FCHUNK * 256];  // num/den partials per (b,chunk)
__device__ float g_coef[BB * CC];            // final per-(b,c) coefficient
__device__ float g_S[BB * ST * CC];          // reflected prefix sums [b][t][c]

// =====================================================================
// K0: prefix sums over reflected time axis. grid 32, 128 thr.
// y[t] = x[t] (t<512) or x[1022-t] (t>=512); S[t] = sum_{s<t} y[s].
// =====================================================================
__global__ void __launch_bounds__(128) k_prefix(const float* __restrict__ x) {
    int b = blockIdx.x, c = threadIdx.x;
    const float* xb = x + (size_t)b * TT * CC + c;
    float* Sb = g_S + (size_t)b * ST * CC + c;
    float run = 0.f;
#pragma unroll 4
    for (int t = 0; t < 576; t++) {
        int src = (t < TT) ? t : (1022 - t);
        Sb[(size_t)t * CC] = run;
        run += xb[(size_t)src * CC];
    }
    Sb[(size_t)576 * CC] = run;
}

// =====================================================================
// K1: direct autocorrelation, lags 8..64. grid (8 chunks, 32 b), 256 thr.
// =====================================================================
#define LOAD8(W, R) { \
    float4 _a = *(const float4*)(xs + (R)*128 + c0); \
    float4 _b = *(const float4*)(xs + (R)*128 + c0 + 4); \
    W[0]=_a.x; W[1]=_a.y; W[2]=_a.z; W[3]=_a.w; \
    W[4]=_b.x; W[5]=_b.y; W[6]=_b.z; W[7]=_b.w; }

__device__ __forceinline__ float dot4x8(const float (&bs)[4][8],
                                        const float* w0, const float* w1,
                                        const float* w2, const float* w3) {
    float s0 = 0.f, s1 = 0.f, s2 = 0.f, s3 = 0.f;
#pragma unroll
    for (int e = 0; e < 8; e++) {
        s0 = fmaf(bs[0][e], w0[e], s0);
        s1 = fmaf(bs[1][e], w1[e], s1);
        s2 = fmaf(bs[2][e], w2[e], s2);
        s3 = fmaf(bs[3][e], w3[e], s3);
    }
    return (s0 + s1) + (s2 + s3);
}

__global__ void __launch_bounds__(256) k_autocorr(const float* __restrict__ x) {
    extern __shared__ float xs[];   // 128 rows * 128 floats = 64KB
    int chunk = blockIdx.x, b = blockIdx.y, tid = threadIdx.x;
    int t0 = chunk * 64;

    for (int i = tid; i < 128 * 32; i += 256) {
        int row = i >> 5, c4 = i & 31;
        int t = (t0 + row) & 511;
        ((float4*)xs)[row * 32 + c4] =
            ((const float4*)(x + ((size_t)b * TT + t) * CC))[c4];
    }
    __syncthreads();

    int cg = tid & 15, tb = tid >> 4;
    int tt0 = tb * 4, c0 = cg * 8;

    float base[4][8];
#pragma unroll
    for (int dt = 0; dt < 4; dt++) { LOAD8(base[dt], tt0 + dt); }

    float acc[57];
#pragma unroll
    for (int j = 0; j < 57; j++) acc[j] = 0.f;

    float w0[8], w1[8], w2[8], w3[8];
    LOAD8(w0, tt0 + 8);
    LOAD8(w1, tt0 + 9);
    LOAD8(w2, tt0 + 10);

#pragma unroll
    for (int j4 = 0; j4 < 56; j4 += 4) {
        LOAD8(w3, tt0 + 11 + j4); acc[j4 + 0] += dot4x8(base, w0, w1, w2, w3);
        LOAD8(w0, tt0 + 12 + j4); acc[j4 + 1] += dot4x8(base, w1, w2, w3, w0);
        LOAD8(w1, tt0 + 13 + j4); acc[j4 + 2] += dot4x8(base, w2, w3, w0, w1);
        LOAD8(w2, tt0 + 14 + j4); acc[j4 + 3] += dot4x8(base, w3, w0, w1, w2);
    }
    LOAD8(w3, tt0 + 67);
    acc[56] += dot4x8(base, w0, w1, w2, w3);

    __syncthreads();
#pragma unroll
    for (int j = 0; j < 57; j++) xs[j * 256 + tid] = acc[j];
    __syncthreads();

    int wid = tid >> 5, lane = tid & 31;
    for (int j = wid; j < 57; j += 8) {
        float s = 0.f;
#pragma unroll
        for (int i = 0; i < 8; i++) s += xs[j * 256 + i * 32 + lane];
#pragma unroll
        for (int off = 16; off; off >>= 1) s += __shfl_xor_sync(0xffffffffu, s, off);
        if (lane == 0) g_rp[(b * NCHUNK + chunk) * 64 + j] = s;
    }
}

// =====================================================================
// K2: reduce chunks, top-3, softmax, entropy -> Gamma. grid 32, 64 thr.
// =====================================================================
__global__ void k_topk() {
    int b = blockIdx.x, tid = threadIdx.x;
    __shared__ float r[64];
    if (tid < NLAG) {
        float s = 0.f;
        for (int ch = 0; ch < NCHUNK; ch++) s += g_rp[(b * NCHUNK + ch) * 64 + tid];
        r[tid] = s * (1.f / 128.f);
    }
    __syncthreads();
    if (tid == 0) {
        int i0 = 0, i1 = 0, i2 = 0;
        float v0 = -3.4e38f, v1 = -3.4e38f, v2 = -3.4e38f;
        for (int j = 0; j < NLAG; j++) if (r[j] > v0) { v0 = r[j]; i0 = j; }
        for (int j = 0; j < NLAG; j++) if (j != i0 && r[j] > v1) { v1 = r[j]; i1 = j; }
        for (int j = 0; j < NLAG; j++) if (j != i0 && j != i1 && r[j] > v2) { v2 = r[j]; i2 = j; }
        float e0 = 1.f, e1 = expf(v1 - v0), e2 = expf(v2 - v0);
        float es = e0 + e1 + e2;
        float q0 = e0 / es, q1 = e1 / es, q2 = e2 / es;
        float H = -(q0 * logf(q0 + 1e-8f) + q1 * logf(q1 + 1e-8f) + q2 * logf(q2 + 1e-8f));
        float Gm = 1.f - H / (logf(3.f + 1e-8f) + 1e-8f);
        Gm = fminf(fmaxf(Gm, 0.f), 1.f);
        g_p[b * 3 + 0] = i0 + 8; g_p[b * 3 + 1] = i1 + 8; g_p[b * 3 + 2] = i2 + 8;
        g_wk[b * 3 + 0] = q0; g_wk[b * 3 + 1] = q1; g_wk[b * 3 + 2] = q2;
        g_gm[b] = Gm;
    }
}

// =====================================================================
// K3: fused per-n pipeline, split 2x along output channels.
// grid (96 n, 2 half), 256 thr. Phase A now reads prefix sums: 2 loads
// per (c,l) instead of up to 64.
// =====================================================================
__global__ void __launch_bounds__(256) k_conv(
    const float* __restrict__ x,
    const float* __restrict__ Wdw,
    const float* __restrict__ Wpw,
    const float* __restrict__ gnw,
    const float* __restrict__ gnb,
    const float* __restrict__ Wg,
    const float* __restrict__ gam)
{
    extern __shared__ float sm[];
    float* u_s    = sm;
    float* h_s    = sm + 8704;
    float* ubar_s = sm + 17408;
    float* gate_s = sm + 17536;
    float* gred   = sm + 17664;
    float* gmean  = sm + 18176;
    float* grstd  = sm + 18192;

    int n = blockIdx.x, half = blockIdx.y, tid = threadIdx.x;
    int b = n / 3;
    int p = g_p[n];
    int n_cyc = (TT + p - 1) / p;

    int warp = tid >> 5, lane = tid & 31;

    // ---- Phase A: u[c][l] = (S[(l+1)p][c] - S[l*p][c]) / 64
    const float* Sb = g_S + (size_t)b * ST * CC;
#pragma unroll
    for (int li = 0; li < 8; li++) {
        int l = warp + li * 8;
        float4 a = make_float4(0.f, 0.f, 0.f, 0.f);
        if (l < n_cyc) {
            float4 s0 = *(const float4*)(Sb + (size_t)(l * p) * CC + lane * 4);
            float4 s1 = *(const float4*)(Sb + (size_t)((l + 1) * p) * CC + lane * 4);
            a.x = s1.x - s0.x; a.y = s1.y - s0.y;
            a.z = s1.z - s0.z; a.w = s1.w - s0.w;
        }
        const float sc = 1.f / 64.f;
        u_s[(lane * 4 + 0) * 68 + l] = a.x * sc;
        u_s[(lane * 4 + 1) * 68 + l] = a.y * sc;
        u_s[(lane * 4 + 2) * 68 + l] = a.z * sc;
        u_s[(lane * 4 + 3) * 68 + l] = a.w * sc;
    }
    __syncthreads();

    if (tid < 128) {
        float s = 0.f;
#pragma unroll
        for (int l = 0; l < 64; l++) s += u_s[tid * 68 + l];
        ubar_s[tid] = s * (1.f / 64.f);
    }
    __syncthreads();

    // ---- dwconv: h[c][l] for all 128 c
    {
        int c = tid >> 1, lh = (tid & 1) * 32;
        float wd[9];
#pragma unroll
        for (int j = 0; j < 9; j++) wd[j] = Wdw[c * 9 + j];
        for (int i = 0; i < 32; i++) {
            int l = lh + i;
            float s = 0.f;
#pragma unroll
            for (int j = 0; j < 9; j++) {
                int ll = l + j - 4;
                if (ll >= 0 && ll < 64) s = fmaf(u_s[c * 68 + ll], wd[j], s);
            }
            h_s[c * 68 + l] = s;
        }
    }

    // ---- gate for this half's 64 o: warp handles 8 o
    {
#pragma unroll
        for (int oi = 0; oi < 8; oi++) {
            int ol = warp * 8 + oi;
            int o = half * 64 + ol;
            float4 wv = *(const float4*)(Wg + (size_t)o * 128 + lane * 4);
            float4 ub = *(const float4*)(ubar_s + lane * 4);
            float s = wv.x * ub.x + wv.y * ub.y + wv.z * ub.z + wv.w * ub.w;
#pragma unroll
            for (int off = 16; off; off >>= 1) s += __shfl_xor_sync(0xffffffffu, s, off);
            if (lane == 0) gate_s[ol] = 1.f / (1.f + expf(-s));
        }
    }
    __syncthreads();

    // ---- pointwise matmul: acc[o][l] = sum_c Wpw[o][c]*h[c][l]
    int og = tid >> 4, lg = tid & 15;
    int o0 = half * 64 + og * 4, l0 = lg * 4;
    float acc[4][4];
#pragma unroll
    for (int i = 0; i < 4; i++)
#pragma unroll
        for (int j = 0; j < 4; j++) acc[i][j] = 0.f;

    for (int cq = 0; cq < 32; cq++) {
        float4 wv[4];
#pragma unroll
        for (int i = 0; i < 4; i++)
            wv[i] = *(const float4*)(Wpw + (size_t)(o0 + i) * 128 + cq * 4);
        float4 h0 = *(const float4*)(h_s + (cq * 4 + 0) * 68 + l0);
        float4 h1 = *(const float4*)(h_s + (cq * 4 + 1) * 68 + l0);
        float4 h2 = *(const float4*)(h_s + (cq * 4 + 2) * 68 + l0);
        float4 h3 = *(const float4*)(h_s + (cq * 4 + 3) * 68 + l0);
#pragma unroll
        for (int i = 0; i < 4; i++) {
            acc[i][0] = fmaf(wv[i].x, h0.x, fmaf(wv[i].y, h1.x, fmaf(wv[i].z, h2.x, fmaf(wv[i].w, h3.x, acc[i][0]))));
            acc[i][1] = fmaf(wv[i].x, h0.y, fmaf(wv[i].y, h1.y, fmaf(wv[i].z, h2.y, fmaf(wv[i].w, h3.y, acc[i][1]))));
            acc[i][2] = fmaf(wv[i].x, h0.z, fmaf(wv[i].y, h1.z, fmaf(wv[i].z, h2.z, fmaf(wv[i].w, h3.z, acc[i][2]))));
            acc[i][3] = fmaf(wv[i].x, h0.w, fmaf(wv[i].y, h1.w, fmaf(wv[i].z, h2.w, fmaf(wv[i].w, h3.w, acc[i][3]))));
        }
    }

    // ---- GroupNorm partials: each og is exactly one group of 4 o
    {
        float s0 = 0.f, ss0 = 0.f;
#pragma unroll
        for (int i = 0; i < 4; i++)
#pragma unroll
            for (int j = 0; j < 4; j++) { s0 += acc[i][j]; ss0 += acc[i][j] * acc[i][j]; }
        gred[og * 16 + lg] = s0;
        gred[256 + og * 16 + lg] = ss0;
    }
    __syncthreads();
    if (tid < 16) {
        float s = 0.f, q = 0.f;
#pragma unroll
        for (int i = 0; i < 16; i++) { s += gred[tid * 16 + i]; q += gred[256 + tid * 16 + i]; }
        float mean = s * (1.f / 256.f);
        float var = q * (1.f / 256.f) - mean * mean;
        gmean[tid] = mean;
        grstd[tid] = rsqrtf(var + 1e-5f);
    }
    __syncthreads();

    // ---- normalize, GELU(exact), * gate * gamma, store [n][l][c]
    {
        float mean = gmean[og], rs = grstd[og];
#pragma unroll
        for (int i = 0; i < 4; i++) {
            int o = o0 + i;
            float gwv = gnw[o], gbv = gnb[o];
            float gm = gam[o] * gate_s[o - half * 64];
#pragma unroll
            for (int j = 0; j < 4; j++) {
                float v = (acc[i][j] - mean) * rs * gwv + gbv;
                float ge = 0.5f * v * (1.f + erff(v * 0.70710678118654752f));
                acc[i][j] = ge * gm;
            }
        }
    }
#pragma unroll
    for (int j = 0; j < 4; j++) {
        float4 v0 = make_float4(acc[0][j], acc[1][j], acc[2][j], acc[3][j]);
        *(float4*)(g_hg + ((size_t)n * 64 + (l0 + j)) * CC + o0) = v0;
    }
}

// =====================================================================
// K4a: num/den partials. grid (32,32), 256 thr. 16 t rows per CTA.
// =====================================================================
__global__ void __launch_bounds__(256) k_dot(const float* __restrict__ x) {
    __shared__ __align__(16) float red[8 * 256];
    int chunk = blockIdx.x, b = blockIdx.y, tid = threadIdx.x;
    int warp = tid >> 5, lane = tid & 31, c0 = lane * 4;
    int p0 = g_p[b * 3 + 0], p1 = g_p[b * 3 + 1], p2 = g_p[b * 3 + 2];
    float w0 = g_wk[b * 3 + 0], w1 = g_wk[b * 3 + 1], w2 = g_wk[b * 3 + 2];
    const float* hg0 = g_hg + (size_t)(b * 3 + 0) * 64 * CC;
    const float* hg1 = g_hg + (size_t)(b * 3 + 1) * 64 * CC;
    const float* hg2 = g_hg + (size_t)(b * 3 + 2) * 64 * CC;
    const float* xb = x + (size_t)b * TT * CC;

    float4 num = make_float4(0.f, 0.f, 0.f, 0.f);
    float4 den = make_float4(0.f, 0.f, 0.f, 0.f);
#pragma unroll
    for (int i = 0; i < 2; i++) {
        int t = chunk * 16 + warp * 2 + i;
        float4 xv = *(const float4*)(xb + (size_t)t * CC + c0);
        float4 a  = *(const float4*)(hg0 + (size_t)(t / p0) * CC + c0);
        float4 bq = *(const float4*)(hg1 + (size_t)(t / p1) * CC + c0);
        float4 cq = *(const float4*)(hg2 + (size_t)(t / p2) * CC + c0);
        float dx0 = w0 * a.x + w1 * bq.x + w2 * cq.x;
        float dx1 = w0 * a.y + w1 * bq.y + w2 * cq.y;
        float dx2 = w0 * a.z + w1 * bq.z + w2 * cq.z;
        float dx3 = w0 * a.w + w1 * bq.w + w2 * cq.w;
        float px0 = xv.x + dx0, px1 = xv.y + dx1, px2 = xv.z + dx2, px3 = xv.w + dx3;
        num.x -= dx0 * px0; num.y -= dx1 * px1; num.z -= dx2 * px2; num.w -= dx3 * px3;
        den.x += px0 * px0; den.y += px1 * px1; den.z += px2 * px2; den.w += px3 * px3;
    }
    *(float4*)(red + warp * 256 + c0)       = num;
    *(float4*)(red + warp * 256 + 128 + c0) = den;
    __syncthreads();
    {
        float s = 0.f;
#pragma unroll
        for (int i = 0; i < 8; i++) s += red[i * 256 + tid];
        g_part[((size_t)b * FCHUNK + chunk) * 256 + tid] = s;
    }
}

// =====================================================================
// K4b: coef[b][c] = Gamma_b * num/(den+1e-6). grid 32, 128 thr.
// =====================================================================
__global__ void k_coef() {
    int b = blockIdx.x, tid = threadIdx.x;
    float sn = 0.f, sd = 0.f;
#pragma unroll
    for (int ch = 0; ch < FCHUNK; ch++) {
        sn += g_part[((size_t)b * FCHUNK + ch) * 256 + tid];
        sd += g_part[((size_t)b * FCHUNK + ch) * 256 + 128 + tid];
    }
    g_coef[b * CC + tid] = g_gm[b] * sn / (sd + 1e-6f);
}

// =====================================================================
// K4c: out = x - coef * (x + d). grid (32,32), 256 thr, 16 t rows/CTA.
// =====================================================================
__global__ void __launch_bounds__(256) k_apply(const float* __restrict__ x,
                                               float* __restrict__ out) {
    int chunk = blockIdx.x, b = blockIdx.y, tid = threadIdx.x;
    int warp = tid >> 5, lane = tid & 31, c0 = lane * 4;
    int p0 = g_p[b * 3 + 0], p1 = g_p[b * 3 + 1], p2 = g_p[b * 3 + 2];
    float w0 = g_wk[b * 3 + 0], w1 = g_wk[b * 3 + 1], w2 = g_wk[b * 3 + 2];
    const float* hg0 = g_hg + (size_t)(b * 3 + 0) * 64 * CC;
    const float* hg1 = g_hg + (size_t)(b * 3 + 1) * 64 * CC;
    const float* hg2 = g_hg + (size_t)(b * 3 + 2) * 64 * CC;
    const float* xb = x + (size_t)b * TT * CC;
    float* ob = out + (size_t)b * TT * CC;

    float4 cf = *(const float4*)(g_coef + b * CC + c0);
#pragma unroll
    for (int i = 0; i < 2; i++) {
        int t = chunk * 16 + warp * 2 + i;
        float4 xv = *(const float4*)(xb + (size_t)t * CC + c0);
        float4 a  = *(const float4*)(hg0 + (size_t)(t / p0) * CC + c0);
        float4 bq = *(const float4*)(hg1 + (size_t)(t / p1) * CC + c0);
        float4 cq = *(const float4*)(hg2 + (size_t)(t / p2) * CC + c0);
        float dx0 = w0 * a.x + w1 * bq.x + w2 * cq.x;
        float dx1 = w0 * a.y + w1 * bq.y + w2 * cq.y;
        float dx2 = w0 * a.z + w1 * bq.z + w2 * cq.z;
        float dx3 = w0 * a.w + w1 * bq.w + w2 * cq.w;
        float4 r;
        r.x = xv.x - cf.x * (xv.x + dx0);
        r.y = xv.y - cf.y * (xv.y + dx1);
        r.z = xv.z - cf.z * (xv.z + dx2);
        r.w = xv.w - cf.w * (xv.w + dx3);
        *(float4*)(ob + (size_t)t * CC + c0) = r;
    }
}

// =====================================================================
extern "C" void kernel_launch(void* const* d_in, const int* in_sizes, int n_in,
                              void* d_out, int out_size) {
    const float* x   = (const float*)d_in[0];
    const float* Wdw = (const float*)d_in[1];
    const float* Wpw = (const float*)d_in[2];
    const float* gnw = (const float*)d_in[3];
    const float* gnb = (const float*)d_in[4];
    const float* Wg  = (const float*)d_in[5];
    const float* gam = (const float*)d_in[6];
    float* out = (float*)d_out;

    cudaFuncSetAttribute(k_autocorr, cudaFuncAttributeMaxDynamicSharedMemorySize, 65536);
    cudaFuncSetAttribute(k_conv, cudaFuncAttributeMaxDynamicSharedMemorySize, 75008);

    dim3 g1(NCHUNK, BB);
    dim3 gc(NN, 2);
    dim3 g2(FCHUNK, BB);
    k_prefix<<<BB, 128>>>(x);
    k_autocorr<<<g1, 256, 65536>>>(x);
    k_topk<<<BB, 64>>>();
    k_conv<<<gc, 256, 75008>>>(x, Wdw, Wpw, gnw, gnb, Wg, gam);
    k_dot<<<g2, 256>>>(x);
    k_coef<<<BB, 128>>>();
    k_apply<<<g2, 256>>>(x, out);
}

// round 10
// speedup vs baseline: 1.4389x; 1.4389x over previous
#include <cuda_runtime.h>
#include <math.h>

// Problem constants: B=32, T=512, C=128, K=3, lags 8..64 (57), CYC_MAX=P_MAX=64,
// KW=9, GN: 32 groups of 4 channels.

#define TT 512
#define CC 128
#define BB 32
#define NN 96           // B*K
#define NLAG 57
#define NCHUNK 8        // autocorr t-chunks
#define FCHUNK 32       // final-stage t-chunks (16 rows each)

// ---------------- device scratch (no allocations allowed) ----------------
__device__ float g_rp[BB * NCHUNK * 64];     // partial autocorr [b][chunk][lag]
__device__ int   g_p[NN];                    // periods
__device__ float g_wk[NN];                   // softmax weights
__device__ float g_gm[BB];                   // Gamma per b
__device__ float g_h[NN * CC * 64];          // dwconv output [n][c][l]
__device__ float g_gate[NN * CC];            // gate [n][o]
__device__ float g_hg[NN * 64 * CC];         // gated conv output [n][l][c]
__device__ float g_part[BB * FCHUNK * 256];  // num/den partials per (b,chunk)
__device__ float g_coef[BB * CC];            // final per-(b,c) coefficient

// =====================================================================
// K1: direct autocorrelation, lags 8..64. grid (8 chunks, 32 b), 256 thr.
// =====================================================================
#define LOAD8(W, R) { \
    float4 _a = *(const float4*)(xs + (R)*128 + c0); \
    float4 _b = *(const float4*)(xs + (R)*128 + c0 + 4); \
    W[0]=_a.x; W[1]=_a.y; W[2]=_a.z; W[3]=_a.w; \
    W[4]=_b.x; W[5]=_b.y; W[6]=_b.z; W[7]=_b.w; }

__device__ __forceinline__ float dot4x8(const float (&bs)[4][8],
                                        const float* w0, const float* w1,
                                        const float* w2, const float* w3) {
    float s0 = 0.f, s1 = 0.f, s2 = 0.f, s3 = 0.f;
#pragma unroll
    for (int e = 0; e < 8; e++) {
        s0 = fmaf(bs[0][e], w0[e], s0);
        s1 = fmaf(bs[1][e], w1[e], s1);
        s2 = fmaf(bs[2][e], w2[e], s2);
        s3 = fmaf(bs[3][e], w3[e], s3);
    }
    return (s0 + s1) + (s2 + s3);
}

__global__ void __launch_bounds__(256) k_autocorr(const float* __restrict__ x) {
    extern __shared__ float xs[];   // 128 rows * 128 floats = 64KB
    int chunk = blockIdx.x, b = blockIdx.y, tid = threadIdx.x;
    int t0 = chunk * 64;

    for (int i = tid; i < 128 * 32; i += 256) {
        int row = i >> 5, c4 = i & 31;
        int t = (t0 + row) & 511;
        ((float4*)xs)[row * 32 + c4] =
            ((const float4*)(x + ((size_t)b * TT + t) * CC))[c4];
    }
    __syncthreads();

    int cg = tid & 15, tb = tid >> 4;
    int tt0 = tb * 4, c0 = cg * 8;

    float base[4][8];
#pragma unroll
    for (int dt = 0; dt < 4; dt++) { LOAD8(base[dt], tt0 + dt); }

    float acc[57];
#pragma unroll
    for (int j = 0; j < 57; j++) acc[j] = 0.f;

    float w0[8], w1[8], w2[8], w3[8];
    LOAD8(w0, tt0 + 8);
    LOAD8(w1, tt0 + 9);
    LOAD8(w2, tt0 + 10);

#pragma unroll
    for (int j4 = 0; j4 < 56; j4 += 4) {
        LOAD8(w3, tt0 + 11 + j4); acc[j4 + 0] += dot4x8(base, w0, w1, w2, w3);
        LOAD8(w0, tt0 + 12 + j4); acc[j4 + 1] += dot4x8(base, w1, w2, w3, w0);
        LOAD8(w1, tt0 + 13 + j4); acc[j4 + 2] += dot4x8(base, w2, w3, w0, w1);
        LOAD8(w2, tt0 + 14 + j4); acc[j4 + 3] += dot4x8(base, w3, w0, w1, w2);
    }
    LOAD8(w3, tt0 + 67);
    acc[56] += dot4x8(base, w0, w1, w2, w3);

    __syncthreads();
#pragma unroll
    for (int j = 0; j < 57; j++) xs[j * 256 + tid] = acc[j];
    __syncthreads();

    int wid = tid >> 5, lane = tid & 31;
    for (int j = wid; j < 57; j += 8) {
        float s = 0.f;
#pragma unroll
        for (int i = 0; i < 8; i++) s += xs[j * 256 + i * 32 + lane];
#pragma unroll
        for (int off = 16; off; off >>= 1) s += __shfl_xor_sync(0xffffffffu, s, off);
        if (lane == 0) g_rp[(b * NCHUNK + chunk) * 64 + j] = s;
    }
}

// =====================================================================
// K2: reduce chunks, top-3, softmax, entropy -> Gamma. grid 32, 64 thr.
// =====================================================================
__global__ void k_topk() {
    int b = blockIdx.x, tid = threadIdx.x;
    __shared__ float r[64];
    if (tid < NLAG) {
        float s = 0.f;
        for (int ch = 0; ch < NCHUNK; ch++) s += g_rp[(b * NCHUNK + ch) * 64 + tid];
        r[tid] = s * (1.f / 128.f);
    }
    __syncthreads();
    if (tid == 0) {
        int i0 = 0, i1 = 0, i2 = 0;
        float v0 = -3.4e38f, v1 = -3.4e38f, v2 = -3.4e38f;
        for (int j = 0; j < NLAG; j++) if (r[j] > v0) { v0 = r[j]; i0 = j; }
        for (int j = 0; j < NLAG; j++) if (j != i0 && r[j] > v1) { v1 = r[j]; i1 = j; }
        for (int j = 0; j < NLAG; j++) if (j != i0 && j != i1 && r[j] > v2) { v2 = r[j]; i2 = j; }
        float e0 = 1.f, e1 = expf(v1 - v0), e2 = expf(v2 - v0);
        float es = e0 + e1 + e2;
        float q0 = e0 / es, q1 = e1 / es, q2 = e2 / es;
        float H = -(q0 * logf(q0 + 1e-8f) + q1 * logf(q1 + 1e-8f) + q2 * logf(q2 + 1e-8f));
        float Gm = 1.f - H / (logf(3.f + 1e-8f) + 1e-8f);
        Gm = fminf(fmaxf(Gm, 0.f), 1.f);
        g_p[b * 3 + 0] = i0 + 8; g_p[b * 3 + 1] = i1 + 8; g_p[b * 3 + 2] = i2 + 8;
        g_wk[b * 3 + 0] = q0; g_wk[b * 3 + 1] = q1; g_wk[b * 3 + 2] = q2;
        g_gm[b] = Gm;
    }
}

// =====================================================================
// K3a: fold + ubar + gate + dwconv, ONCE per n. grid 96, 512 thr.
// 16 warps: warp w covers l = w, w+16, w+32, w+48; lanes cover c-quads.
// pos loop unrolled with 4 independent float4 accumulators (MLP ~8).
// Writes h[n][c][l] and gate[n][o] to global.
// smem: u 128x68 (8704 fl) + ubar 128 = 8832 floats = 35328 B.
// =====================================================================
#define XROW(P) (*(const float4*)(xb + (size_t)((P) < TT ? (P) : (1022 - (P))) * CC + lane * 4))

__global__ void __launch_bounds__(512) k_fold(const float* __restrict__ x,
                                              const float* __restrict__ Wdw,
                                              const float* __restrict__ Wg) {
    extern __shared__ float sf[];
    float* u_s    = sf;          // 128 x 68
    float* ubar_s = sf + 8704;   // 128

    int n = blockIdx.x, tid = threadIdx.x;
    int b = n / 3;
    int p = g_p[n];
    int n_cyc = (TT + p - 1) / p;
    const float* xb = x + (size_t)b * TT * CC;
    int warp = tid >> 5, lane = tid & 31;

    // ---- u[c][l] = (1/64) * sum_{pos<p} x_reflect[l*p+pos, c]
#pragma unroll
    for (int j = 0; j < 4; j++) {
        int l = warp + j * 16;
        float4 a0 = make_float4(0.f,0.f,0.f,0.f), a1 = a0, a2 = a0, a3 = a0;
        if (l < n_cyc) {
            int pos = l * p, pend = l * p + p;
#pragma unroll 2
            for (; pos + 4 <= pend; pos += 4) {
                float4 v0 = XROW(pos);
                float4 v1 = XROW(pos + 1);
                float4 v2 = XROW(pos + 2);
                float4 v3 = XROW(pos + 3);
                a0.x += v0.x; a0.y += v0.y; a0.z += v0.z; a0.w += v0.w;
                a1.x += v1.x; a1.y += v1.y; a1.z += v1.z; a1.w += v1.w;
                a2.x += v2.x; a2.y += v2.y; a2.z += v2.z; a2.w += v2.w;
                a3.x += v3.x; a3.y += v3.y; a3.z += v3.z; a3.w += v3.w;
            }
            for (; pos < pend; pos++) {
                float4 v = XROW(pos);
                a0.x += v.x; a0.y += v.y; a0.z += v.z; a0.w += v.w;
            }
        }
        const float sc = 1.f / 64.f;
        float ux = ((a0.x + a1.x) + (a2.x + a3.x)) * sc;
        float uy = ((a0.y + a1.y) + (a2.y + a3.y)) * sc;
        float uz = ((a0.z + a1.z) + (a2.z + a3.z)) * sc;
        float uw = ((a0.w + a1.w) + (a2.w + a3.w)) * sc;
        u_s[(lane * 4 + 0) * 68 + l] = ux;
        u_s[(lane * 4 + 1) * 68 + l] = uy;
        u_s[(lane * 4 + 2) * 68 + l] = uz;
        u_s[(lane * 4 + 3) * 68 + l] = uw;
    }
    __syncthreads();

    // ---- ubar[c] = mean_l u[c][l]
    if (tid < 128) {
        float s = 0.f;
#pragma unroll
        for (int l = 0; l < 64; l++) s += u_s[tid * 68 + l];
        ubar_s[tid] = s * (1.f / 64.f);
    }
    __syncthreads();

    // ---- gate[o] = sigmoid(Wg[o]·ubar); warp handles 8 o (16 warps x 8 = 128)
    {
#pragma unroll
        for (int oi = 0; oi < 8; oi++) {
            int o = warp * 8 + oi;
            float4 wv = *(const float4*)(Wg + (size_t)o * 128 + lane * 4);
            float4 ub = *(const float4*)(ubar_s + lane * 4);
            float s = wv.x * ub.x + wv.y * ub.y + wv.z * ub.z + wv.w * ub.w;
#pragma unroll
            for (int off = 16; off; off >>= 1) s += __shfl_xor_sync(0xffffffffu, s, off);
            if (lane == 0) g_gate[n * CC + o] = 1.f / (1.f + expf(-s));
        }
    }

    // ---- dwconv: h[c][l] -> global g_h[n][c][l]
    {
        int c = tid >> 2, lh = (tid & 3) * 16;
        float wd[9];
#pragma unroll
        for (int j = 0; j < 9; j++) wd[j] = Wdw[c * 9 + j];
        float* hrow = g_h + ((size_t)n * CC + c) * 64;
#pragma unroll
        for (int i = 0; i < 16; i++) {
            int l = lh + i;
            float s = 0.f;
#pragma unroll
            for (int j = 0; j < 9; j++) {
                int ll = l + j - 4;
                if (ll >= 0 && ll < 64) s = fmaf(u_s[c * 68 + ll], wd[j], s);
            }
            hrow[l] = s;
        }
    }
}

// =====================================================================
// K3b: pointwise matmul + GroupNorm + GELU + gate + store.
// grid (96 n, 2 half), 256 thr. Loads h tile from global (L2) to smem.
// smem: h 128x68 (8704) + gate 64 + gred 512 + stats 32 = 9312 fl = 37248 B
// =====================================================================
__global__ void __launch_bounds__(256) k_mm(
    const float* __restrict__ Wpw,
    const float* __restrict__ gnw,
    const float* __restrict__ gnb,
    const float* __restrict__ gam)
{
    extern __shared__ float sm[];
    float* h_s    = sm;          // 128 x 68
    float* gate_s = sm + 8704;   // 64
    float* gred   = sm + 8768;   // 512
    float* gmean  = sm + 9280;   // 16
    float* grstd  = sm + 9296;   // 16

    int n = blockIdx.x, half = blockIdx.y, tid = threadIdx.x;

    // ---- load h tile [128 c][64 l] coalesced
    const float4* hg4 = (const float4*)(g_h + (size_t)n * CC * 64);
#pragma unroll
    for (int i = 0; i < 8; i++) {
        int lin = tid + i * 256;          // float4 index, 0..2047
        int c = lin >> 4, l4 = lin & 15;
        *(float4*)(h_s + c * 68 + l4 * 4) = hg4[lin];
    }
    if (tid < 64) gate_s[tid] = g_gate[n * CC + half * 64 + tid];
    __syncthreads();

    // ---- pointwise matmul: acc[o][l] = sum_c Wpw[o][c]*h[c][l]
    int og = tid >> 4, lg = tid & 15;
    int o0 = half * 64 + og * 4, l0 = lg * 4;
    float acc[4][4];
#pragma unroll
    for (int i = 0; i < 4; i++)
#pragma unroll
        for (int j = 0; j < 4; j++) acc[i][j] = 0.f;

    for (int cq = 0; cq < 32; cq++) {
        float4 wv[4];
#pragma unroll
        for (int i = 0; i < 4; i++)
            wv[i] = *(const float4*)(Wpw + (size_t)(o0 + i) * 128 + cq * 4);
        float4 h0 = *(const float4*)(h_s + (cq * 4 + 0) * 68 + l0);
        float4 h1 = *(const float4*)(h_s + (cq * 4 + 1) * 68 + l0);
        float4 h2 = *(const float4*)(h_s + (cq * 4 + 2) * 68 + l0);
        float4 h3 = *(const float4*)(h_s + (cq * 4 + 3) * 68 + l0);
#pragma unroll
        for (int i = 0; i < 4; i++) {
            acc[i][0] = fmaf(wv[i].x, h0.x, fmaf(wv[i].y, h1.x, fmaf(wv[i].z, h2.x, fmaf(wv[i].w, h3.x, acc[i][0]))));
            acc[i][1] = fmaf(wv[i].x, h0.y, fmaf(wv[i].y, h1.y, fmaf(wv[i].z, h2.y, fmaf(wv[i].w, h3.y, acc[i][1]))));
            acc[i][2] = fmaf(wv[i].x, h0.z, fmaf(wv[i].y, h1.z, fmaf(wv[i].z, h2.z, fmaf(wv[i].w, h3.z, acc[i][2]))));
            acc[i][3] = fmaf(wv[i].x, h0.w, fmaf(wv[i].y, h1.w, fmaf(wv[i].z, h2.w, fmaf(wv[i].w, h3.w, acc[i][3]))));
        }
    }

    // ---- GroupNorm partials: each og is exactly one group of 4 o
    {
        float s0 = 0.f, ss0 = 0.f;
#pragma unroll
        for (int i = 0; i < 4; i++)
#pragma unroll
            for (int j = 0; j < 4; j++) { s0 += acc[i][j]; ss0 += acc[i][j] * acc[i][j]; }
        gred[og * 16 + lg] = s0;
        gred[256 + og * 16 + lg] = ss0;
    }
    __syncthreads();
    if (tid < 16) {
        float s = 0.f, q = 0.f;
#pragma unroll
        for (int i = 0; i < 16; i++) { s += gred[tid * 16 + i]; q += gred[256 + tid * 16 + i]; }
        float mean = s * (1.f / 256.f);
        float var = q * (1.f / 256.f) - mean * mean;
        gmean[tid] = mean;
        grstd[tid] = rsqrtf(var + 1e-5f);
    }
    __syncthreads();

    // ---- normalize, GELU(exact), * gate * gamma, store [n][l][c]
    {
        float mean = gmean[og], rs = grstd[og];
#pragma unroll
        for (int i = 0; i < 4; i++) {
            int o = o0 + i;
            float gwv = gnw[o], gbv = gnb[o];
            float gm = gam[o] * gate_s[o - half * 64];
#pragma unroll
            for (int j = 0; j < 4; j++) {
                float v = (acc[i][j] - mean) * rs * gwv + gbv;
                float ge = 0.5f * v * (1.f + erff(v * 0.70710678118654752f));
                acc[i][j] = ge * gm;
            }
        }
    }
#pragma unroll
    for (int j = 0; j < 4; j++) {
        float4 v0 = make_float4(acc[0][j], acc[1][j], acc[2][j], acc[3][j]);
        *(float4*)(g_hg + ((size_t)n * 64 + (l0 + j)) * CC + o0) = v0;
    }
}

// =====================================================================
// K4a: num/den partials. grid (32,32), 256 thr. 16 t rows per CTA.
// =====================================================================
__global__ void __launch_bounds__(256) k_dot(const float* __restrict__ x) {
    __shared__ __align__(16) float red[8 * 256];
    int chunk = blockIdx.x, b = blockIdx.y, tid = threadIdx.x;
    int warp = tid >> 5, lane = tid & 31, c0 = lane * 4;
    int p0 = g_p[b * 3 + 0], p1 = g_p[b * 3 + 1], p2 = g_p[b * 3 + 2];
    float w0 = g_wk[b * 3 + 0], w1 = g_wk[b * 3 + 1], w2 = g_wk[b * 3 + 2];
    const float* hg0 = g_hg + (size_t)(b * 3 + 0) * 64 * CC;
    const float* hg1 = g_hg + (size_t)(b * 3 + 1) * 64 * CC;
    const float* hg2 = g_hg + (size_t)(b * 3 + 2) * 64 * CC;
    const float* xb = x + (size_t)b * TT * CC;

    float4 num = make_float4(0.f, 0.f, 0.f, 0.f);
    float4 den = make_float4(0.f, 0.f, 0.f, 0.f);
#pragma unroll
    for (int i = 0; i < 2; i++) {
        int t = chunk * 16 + warp * 2 + i;
        float4 xv = *(const float4*)(xb + (size_t)t * CC + c0);
        float4 a  = *(const float4*)(hg0 + (size_t)(t / p0) * CC + c0);
        float4 bq = *(const float4*)(hg1 + (size_t)(t / p1) * CC + c0);
        float4 cq = *(const float4*)(hg2 + (size_t)(t / p2) * CC + c0);
        float dx0 = w0 * a.x + w1 * bq.x + w2 * cq.x;
        float dx1 = w0 * a.y + w1 * bq.y + w2 * cq.y;
        float dx2 = w0 * a.z + w1 * bq.z + w2 * cq.z;
        float dx3 = w0 * a.w + w1 * bq.w + w2 * cq.w;
        float px0 = xv.x + dx0, px1 = xv.y + dx1, px2 = xv.z + dx2, px3 = xv.w + dx3;
        num.x -= dx0 * px0; num.y -= dx1 * px1; num.z -= dx2 * px2; num.w -= dx3 * px3;
        den.x += px0 * px0; den.y += px1 * px1; den.z += px2 * px2; den.w += px3 * px3;
    }
    *(float4*)(red + warp * 256 + c0)       = num;
    *(float4*)(red + warp * 256 + 128 + c0) = den;
    __syncthreads();
    {
        float s = 0.f;
#pragma unroll
        for (int i = 0; i < 8; i++) s += red[i * 256 + tid];
        g_part[((size_t)b * FCHUNK + chunk) * 256 + tid] = s;
    }
}

// =====================================================================
// K4b: coef[b][c] = Gamma_b * num/(den+1e-6). grid 32, 128 thr.
// =====================================================================
__global__ void k_coef() {
    int b = blockIdx.x, tid = threadIdx.x;
    float sn = 0.f, sd = 0.f;
#pragma unroll
    for (int ch = 0; ch < FCHUNK; ch++) {
        sn += g_part[((size_t)b * FCHUNK + ch) * 256 + tid];
        sd += g_part[((size_t)b * FCHUNK + ch) * 256 + 128 + tid];
    }
    g_coef[b * CC + tid] = g_gm[b] * sn / (sd + 1e-6f);
}

// =====================================================================
// K4c: out = x - coef * (x + d). grid (32,32), 256 thr, 16 t rows/CTA.
// =====================================================================
__global__ void __launch_bounds__(256) k_apply(const float* __restrict__ x,
                                               float* __restrict__ out) {
    int chunk = blockIdx.x, b = blockIdx.y, tid = threadIdx.x;
    int warp = tid >> 5, lane = tid & 31, c0 = lane * 4;
    int p0 = g_p[b * 3 + 0], p1 = g_p[b * 3 + 1], p2 = g_p[b * 3 + 2];
    float w0 = g_wk[b * 3 + 0], w1 = g_wk[b * 3 + 1], w2 = g_wk[b * 3 + 2];
    const float* hg0 = g_hg + (size_t)(b * 3 + 0) * 64 * CC;
    const float* hg1 = g_hg + (size_t)(b * 3 + 1) * 64 * CC;
    const float* hg2 = g_hg + (size_t)(b * 3 + 2) * 64 * CC;
    const float* xb = x + (size_t)b * TT * CC;
    float* ob = out + (size_t)b * TT * CC;

    float4 cf = *(const float4*)(g_coef + b * CC + c0);
#pragma unroll
    for (int i = 0; i < 2; i++) {
        int t = chunk * 16 + warp * 2 + i;
        float4 xv = *(const float4*)(xb + (size_t)t * CC + c0);
        float4 a  = *(const float4*)(hg0 + (size_t)(t / p0) * CC + c0);
        float4 bq = *(const float4*)(hg1 + (size_t)(t / p1) * CC + c0);
        float4 cq = *(const float4*)(hg2 + (size_t)(t / p2) * CC + c0);
        float dx0 = w0 * a.x + w1 * bq.x + w2 * cq.x;
        float dx1 = w0 * a.y + w1 * bq.y + w2 * cq.y;
        float dx2 = w0 * a.z + w1 * bq.z + w2 * cq.z;
        float dx3 = w0 * a.w + w1 * bq.w + w2 * cq.w;
        float4 r;
        r.x = xv.x - cf.x * (xv.x + dx0);
        r.y = xv.y - cf.y * (xv.y + dx1);
        r.z = xv.z - cf.z * (xv.z + dx2);
        r.w = xv.w - cf.w * (xv.w + dx3);
        *(float4*)(ob + (size_t)t * CC + c0) = r;
    }
}

// =====================================================================
extern "C" void kernel_launch(void* const* d_in, const int* in_sizes, int n_in,
                              void* d_out, int out_size) {
    const float* x   = (const float*)d_in[0];
    const float* Wdw = (const float*)d_in[1];
    const float* Wpw = (const float*)d_in[2];
    const float* gnw = (const float*)d_in[3];
    const float* gnb = (const float*)d_in[4];
    const float* Wg  = (const float*)d_in[5];
    const float* gam = (const float*)d_in[6];
    float* out = (float*)d_out;

    cudaFuncSetAttribute(k_autocorr, cudaFuncAttributeMaxDynamicSharedMemorySize, 65536);
    cudaFuncSetAttribute(k_fold, cudaFuncAttributeMaxDynamicSharedMemorySize, 35328);
    cudaFuncSetAttribute(k_mm, cudaFuncAttributeMaxDynamicSharedMemorySize, 37248);

    dim3 g1(NCHUNK, BB);
    dim3 gm(NN, 2);
    dim3 g2(FCHUNK, BB);
    k_autocorr<<<g1, 256, 65536>>>(x);
    k_topk<<<BB, 64>>>();
    k_fold<<<NN, 512, 35328>>>(x, Wdw, Wg);
    k_mm<<<gm, 256, 37248>>>(Wpw, gnw, gnb, gam);
    k_dot<<<g2, 256>>>(x);
    k_coef<<<BB, 128>>>();
    k_apply<<<g2, 256>>>(x, out);
}